// round 6
// baseline (speedup 1.0000x reference)
#include <cuda_runtime.h>
#include <cuda_bf16.h>

// HopfieldTSP: x_1000 = sign(w @ x0). Iterations 2..1000 are a provable fixed
// point (diagonal 2*rowsum_i ~ 8192 dominates |sum_j adj_ij*(+-1)| <= rowsum_i),
// so one fused pass computes rowsum_i and dot_i = (adj@x0)_i, then
//   s_i = (2*rowsum_i + adj_ii)*x0_i - dot_i ;  out_i = sign(s_i).
//
// R6: chip-shared memory path is the binder (R2==R5 despite 16%-vs-1% SM
// imbalance). Move the adj stream to the pattern that hits the measured LTS
// cap: __ldcg (L2-only, no L1 allocation -> L1 reserved for x) + deeper
// front-batched MLP (unroll 8, ptxas reorders). SM-side shape unchanged.

#define N_CITIES 8192
#define THREADS 256
#define ROWS_PER_BLOCK (THREADS / 32)   // 8
#define ROW4 (N_CITIES / 4)             // 2048 float4 per row

__global__ void __launch_bounds__(THREADS, 8)
hopfield_fused_kernel(const float* __restrict__ adj,
                      const float* __restrict__ x,
                      float* __restrict__ out) {
    const int warp = threadIdx.x >> 5;
    const int lane = threadIdx.x & 31;
    const int row  = blockIdx.x * ROWS_PER_BLOCK + warp;

    const float4* arow = reinterpret_cast<const float4*>(adj + (size_t)row * N_CITIES);
    const float4* x4   = reinterpret_cast<const float4*>(x);

    // 64 trips per lane. adj: __ldcg streams through L2 only (zero L1
    // allocation); x: __ldg, hot in an L1 it now owns exclusively.
    float rs = 0.0f, dot = 0.0f;
    #pragma unroll 8
    for (int j = lane; j < ROW4; j += 32) {
        float4 a  = __ldcg(&arow[j]);
        float4 xv = __ldg(&x4[j]);
        rs  += (a.x + a.y) + (a.z + a.w);
        dot += a.x * xv.x + a.y * xv.y + a.z * xv.z + a.w * xv.w;
    }

    #pragma unroll
    for (int o = 16; o > 0; o >>= 1) {
        rs  += __shfl_xor_sync(0xFFFFFFFFu, rs, o);
        dot += __shfl_xor_sync(0xFFFFFFFFu, dot, o);
    }

    if (lane == 0) {
        float aii = __ldg(adj + (size_t)row * N_CITIES + row);
        float xi  = __ldg(x + row);
        float s   = (2.0f * rs + aii) * xi - dot;
        out[row] = (s > 0.0f) ? 1.0f : ((s < 0.0f) ? -1.0f : 0.0f);
    }
}

extern "C" void kernel_launch(void* const* d_in, const int* in_sizes, int n_in,
                              void* d_out, int out_size) {
    const float* adj = (const float*)d_in[0];   // [8192, 8192] fp32 row-major
    const float* x   = (const float*)d_in[1];   // [8192] fp32
    float* out       = (float*)d_out;           // [8192] fp32

    hopfield_fused_kernel<<<N_CITIES / ROWS_PER_BLOCK, THREADS>>>(adj, x, out);
}